// round 1
// baseline (speedup 1.0000x reference)
#include <cuda_runtime.h>

// Problem: x <- gelu(x + depthwise_conv3d_3x3x3(x)) repeated 8 times.
// Shapes: x [4,32,64,64,64] fp32, weight [32,1,3,3,3] fp32, depth = 8 (constant).

#define CC   32
#define VOL  (64*64*64)

// Ping-pong scratch (static __device__, no allocations).
__device__ float g_scratch[4 * CC * VOL];

// ---------- packed f32x2 helpers ----------
__device__ __forceinline__ unsigned long long pack2(float lo, float hi) {
    unsigned long long r;
    asm("mov.b64 %0, {%1, %2};" : "=l"(r) : "f"(lo), "f"(hi));
    return r;
}
__device__ __forceinline__ void unpack2(unsigned long long v, float& lo, float& hi) {
    asm("mov.b64 {%0, %1}, %2;" : "=f"(lo), "=f"(hi) : "l"(v));
}
__device__ __forceinline__ void fma2(unsigned long long& acc,
                                     unsigned long long a, unsigned long long b) {
    asm("fma.rn.f32x2 %0, %1, %2, %0;" : "+l"(acc) : "l"(a), "l"(b));
}
__device__ __forceinline__ unsigned long long add2(unsigned long long a, unsigned long long b) {
    unsigned long long r;
    asm("add.rn.f32x2 %0, %1, %2;" : "=l"(r) : "l"(a), "l"(b));
    return r;
}

// Exact-erf GELU via Abramowitz-Stegun 7.1.26 (max abs err ~1.5e-7, far below 1e-3 tol).
__device__ __forceinline__ float gelu_exact(float x) {
    float z = x * 0.70710678118654752440f;
    float a = fabsf(z);
    float d = fmaf(0.3275911f, a, 1.0f);
    float t; asm("rcp.approx.f32 %0, %1;" : "=f"(t) : "f"(d));
    float p = fmaf(t, 1.061405429f, -1.453152027f);
    p = fmaf(t, p, 1.421413741f);
    p = fmaf(t, p, -0.284496736f);
    p = fmaf(t, p, 0.254829592f);
    p = p * t;
    float e; asm("ex2.approx.f32 %0, %1;" : "=f"(e) : "f"(-a * a * 1.4426950408889634f));
    float er = fmaf(-p, e, 1.0f);       // erf(|z|)
    er = copysignf(er, z);
    return 0.5f * fmaf(x, er, x);       // 0.5*x*(1+erf(x/sqrt(2)))
}

// One propagation step.
// Block: (h_chunk, c, b); 256 threads (16 w-quads x 16 h-rows); streams all 64 D-planes.
// 3-stage f32x2 accumulator pipeline: each plane read from SMEM once,
// contributing taps kz=2 -> out(p-1), kz=1 -> out(p), kz=0 -> out(p+1).
__global__ void __launch_bounds__(256, 2)
step_kernel(const float* __restrict__ in, float* __restrict__ out,
            const float* __restrict__ wts)
{
    const int tx  = threadIdx.x;           // 0..15, w quad (4 outputs each)
    const int ty  = threadIdx.y;           // 0..15, h row within chunk
    const int tid = ty * 16 + tx;
    const int h0  = blockIdx.x * 16;
    const int c   = blockIdx.y;
    const int b   = blockIdx.z;

    const float* vin  = in  + (size_t)(b * CC + c) * VOL;
    float*       vout = out + (size_t)(b * CC + c) * VOL;

    // 27 weights, duplicated into f32x2 pairs (uniform per block).
    unsigned long long W2[27];
#pragma unroll
    for (int i = 0; i < 27; ++i) {
        float w = __ldg(&wts[c * 27 + i]);
        W2[i] = pack2(w, w);
    }

    // Two ping-pong H-slabs with W-halo: 18 rows x 66 cols.
    __shared__ float slab[2][18 * 66];
    if (tid < 36) {                        // zero the W-halo columns once
        int bf = tid / 18, r = tid % 18;
        slab[bf][r * 66 + 0]  = 0.f;
        slab[bf][r * 66 + 65] = 0.f;
    }

    // Loader assignment: 18x64 floats = 288 float4s; thread tid does float4 #tid,
    // threads 0..31 also do #256+tid.
    const int  r0  = tid >> 4, cq = tid & 15;
    const int  gh0 = h0 - 1 + r0;
    const bool v0  = (gh0 >= 0) && (gh0 < 64);
    const float4* s0 = (const float4*)vin + gh0 * 16 + cq;
    const int  dst0  = r0 * 66 + 1 + 4 * cq;

    const int  r1  = 16 + (tid >> 4);      // rows 16,17 (tid<32 only)
    const int  gh1 = h0 - 1 + r1;
    const bool v1  = (tid < 32) && (gh1 < 64);
    const float4* s1 = (const float4*)vin + gh1 * 16 + cq;
    const int  dst1  = r1 * 66 + 1 + 4 * cq;

    float4 va = make_float4(0.f, 0.f, 0.f, 0.f);
    float4 vb = make_float4(0.f, 0.f, 0.f, 0.f);
    if (v0) va = __ldg(s0);
    if (v1) vb = __ldg(s1);

    unsigned long long accA0 = 0, accA1 = 0;   // completing out(p-1)  (kz=2 taps)
    unsigned long long accB0 = 0, accB1 = 0;   // out(p)               (kz=1 taps)
    unsigned long long accC0 = 0, accC1 = 0;   // out(p+1)             (kz=0 taps)
    unsigned long long cenP0 = 0, cenP1 = 0;   // residual centers of plane p-1

    const int outRow = (h0 + ty) * 64 + 4 * tx;

#pragma unroll 1
    for (int p = 0; p < 64; ++p) {
        float* sb = slab[p & 1];
        sb[dst0 + 0] = va.x; sb[dst0 + 1] = va.y;
        sb[dst0 + 2] = va.z; sb[dst0 + 3] = va.w;
        if (tid < 32) {
            sb[dst1 + 0] = vb.x; sb[dst1 + 1] = vb.y;
            sb[dst1 + 2] = vb.z; sb[dst1 + 3] = vb.w;
        }
        if (p < 63) {                      // prefetch next plane; overlaps compute
            va = v0 ? __ldg(s0 + (p + 1) * 1024) : make_float4(0.f, 0.f, 0.f, 0.f);
            if (tid < 32)
                vb = v1 ? __ldg(s1 + (p + 1) * 1024) : make_float4(0.f, 0.f, 0.f, 0.f);
        }
        __syncthreads();

        unsigned long long cenC0 = 0, cenC1 = 0;
#pragma unroll
        for (int r = 0; r < 3; ++r) {      // r == ky
            const float2* rp = (const float2*)&sb[(ty + r) * 66 + 4 * tx];
            float2 q0 = rp[0], q1 = rp[1], q2 = rp[2];
            unsigned long long P0 = pack2(q0.x, q0.y);
            unsigned long long P1 = pack2(q0.y, q1.x);
            unsigned long long P2 = pack2(q1.x, q1.y);
            unsigned long long P3 = pack2(q1.y, q2.x);
            unsigned long long P4 = pack2(q2.x, q2.y);
            if (r == 1) { cenC0 = P1; cenC1 = P3; }   // centers for residual

            // kz=2 -> accA (out p-1)
            fma2(accA0, W2[18 + r * 3 + 0], P0);
            fma2(accA0, W2[18 + r * 3 + 1], P1);
            fma2(accA0, W2[18 + r * 3 + 2], P2);
            fma2(accA1, W2[18 + r * 3 + 0], P2);
            fma2(accA1, W2[18 + r * 3 + 1], P3);
            fma2(accA1, W2[18 + r * 3 + 2], P4);
            // kz=1 -> accB (out p)
            fma2(accB0, W2[9 + r * 3 + 0], P0);
            fma2(accB0, W2[9 + r * 3 + 1], P1);
            fma2(accB0, W2[9 + r * 3 + 2], P2);
            fma2(accB1, W2[9 + r * 3 + 0], P2);
            fma2(accB1, W2[9 + r * 3 + 1], P3);
            fma2(accB1, W2[9 + r * 3 + 2], P4);
            // kz=0 -> accC (out p+1)
            fma2(accC0, W2[0 + r * 3 + 0], P0);
            fma2(accC0, W2[0 + r * 3 + 1], P1);
            fma2(accC0, W2[0 + r * 3 + 2], P2);
            fma2(accC1, W2[0 + r * 3 + 0], P2);
            fma2(accC1, W2[0 + r * 3 + 1], P3);
            fma2(accC1, W2[0 + r * 3 + 2], P4);
        }

        if (p > 0) {                       // out(p-1) is complete
            unsigned long long u0 = add2(accA0, cenP0);
            unsigned long long u1 = add2(accA1, cenP1);
            float o0, o1, o2, o3;
            unpack2(u0, o0, o1);
            unpack2(u1, o2, o3);
            float4 ov = make_float4(gelu_exact(o0), gelu_exact(o1),
                                    gelu_exact(o2), gelu_exact(o3));
            *(float4*)&vout[(p - 1) * 4096 + outRow] = ov;
        }
        // rotate pipeline
        accA0 = accB0; accA1 = accB1;
        accB0 = accC0; accB1 = accC1;
        accC0 = 0;     accC1 = 0;
        cenP0 = cenC0; cenP1 = cenC1;
    }

    // out(63): planes 62,63 accumulated; plane 64 is zero padding.
    {
        unsigned long long u0 = add2(accA0, cenP0);
        unsigned long long u1 = add2(accA1, cenP1);
        float o0, o1, o2, o3;
        unpack2(u0, o0, o1);
        unpack2(u1, o2, o3);
        float4 ov = make_float4(gelu_exact(o0), gelu_exact(o1),
                                gelu_exact(o2), gelu_exact(o3));
        *(float4*)&vout[63 * 4096 + outRow] = ov;
    }
}

extern "C" void kernel_launch(void* const* d_in, const int* in_sizes, int n_in,
                              void* d_out, int out_size)
{
    const float* x = (const float*)d_in[0];
    const float* w = (const float*)d_in[1];
    float* out = (float*)d_out;

    float* scratch = nullptr;
    cudaGetSymbolAddress((void**)&scratch, g_scratch);

    dim3 grid(4, CC, 4);    // (h-chunks, C, B)
    dim3 blk(16, 16);

    // depth = 8 (constant per setup_inputs). Ping-pong: even steps -> scratch,
    // odd steps -> d_out; step 7 lands in d_out.
    step_kernel<<<grid, blk>>>(x,       scratch, w);
    step_kernel<<<grid, blk>>>(scratch, out,     w);
    step_kernel<<<grid, blk>>>(out,     scratch, w);
    step_kernel<<<grid, blk>>>(scratch, out,     w);
    step_kernel<<<grid, blk>>>(out,     scratch, w);
    step_kernel<<<grid, blk>>>(scratch, out,     w);
    step_kernel<<<grid, blk>>>(out,     scratch, w);
    step_kernel<<<grid, blk>>>(scratch, out,     w);
}

// round 2
// speedup vs baseline: 1.0143x; 1.0143x over previous
#include <cuda_runtime.h>

// x <- gelu(x + depthwise_conv3d_3x3x3(x)) x8.  [4,32,64,64,64] fp32.

#define CC   32
#define VOL  (64*64*64)

typedef unsigned long long u64;

// Two ping-pong scratches, padded by one D-plane (4096 floats) so the
// steady-state kernel may prefetch "plane 64" unguarded.
__device__ float  g_sA[4 * CC * VOL + 4096];
__device__ float  g_sB[4 * CC * VOL + 4096];
__device__ float4 g_zero4 = {0.f, 0.f, 0.f, 0.f};

// ---------- packed f32x2 helpers ----------
__device__ __forceinline__ u64 pack2(float lo, float hi) {
    u64 r; asm("mov.b64 %0, {%1, %2};" : "=l"(r) : "f"(lo), "f"(hi)); return r;
}
__device__ __forceinline__ void unpack2(u64 v, float& lo, float& hi) {
    asm("mov.b64 {%0, %1}, %2;" : "=f"(lo), "=f"(hi) : "l"(v));
}
__device__ __forceinline__ void fma2(u64& acc, u64 a, u64 b) {
    asm("fma.rn.f32x2 %0, %1, %2, %0;" : "+l"(acc) : "l"(a), "l"(b));
}
__device__ __forceinline__ void mul2(u64& d, u64 a, u64 b) {
    asm("mul.rn.f32x2 %0, %1, %2;" : "=l"(d) : "l"(a), "l"(b));
}
__device__ __forceinline__ u64 add2(u64 a, u64 b) {
    u64 r; asm("add.rn.f32x2 %0, %1, %2;" : "=l"(r) : "l"(a), "l"(b)); return r;
}

// Exact-erf GELU via A&S 7.1.26 (abs err ~1.5e-7).
__device__ __forceinline__ float gelu_exact(float x) {
    float z = x * 0.70710678118654752440f;
    float a = fabsf(z);
    float d = fmaf(0.3275911f, a, 1.0f);
    float t; asm("rcp.approx.f32 %0, %1;" : "=f"(t) : "f"(d));
    float p = fmaf(t, 1.061405429f, -1.453152027f);
    p = fmaf(t, p, 1.421413741f);
    p = fmaf(t, p, -0.284496736f);
    p = fmaf(t, p, 0.254829592f);
    p = p * t;
    float e; asm("ex2.approx.f32 %0, %1;" : "=f"(e) : "f"(-a * a * 1.4426950408889634f));
    float er = fmaf(-p, e, 1.0f);
    er = copysignf(er, z);
    return 0.5f * fmaf(x, er, x);
}

// Row body for one ky: loads 3 aligned float2 from SMEM, builds 5 f32x2 windows,
// feeds 18 fma2 into three accumulators (X completes, Y mid, Z fresh at FIRST==row0).
#define ROW(RBASE, OFF, WX, WY, WZ, FIRSTZ, CAPC)                                   \
    {                                                                               \
        float2 q0 = *(const float2*)((RBASE) + (OFF) + 0);                          \
        float2 q1 = *(const float2*)((RBASE) + (OFF) + 2);                          \
        float2 q2 = *(const float2*)((RBASE) + (OFF) + 4);                          \
        u64 P0 = pack2(q0.x, q0.y), P1 = pack2(q0.y, q1.x), P2 = pack2(q1.x, q1.y); \
        u64 P3 = pack2(q1.y, q2.x), P4 = pack2(q2.x, q2.y);                         \
        if (CAPC) { CN0 = P1; CN1 = P3; }                                           \
        fma2(X0, W2[WX+0], P0); fma2(X0, W2[WX+1], P1); fma2(X0, W2[WX+2], P2);     \
        fma2(X1, W2[WX+0], P2); fma2(X1, W2[WX+1], P3); fma2(X1, W2[WX+2], P4);     \
        fma2(Y0, W2[WY+0], P0); fma2(Y0, W2[WY+1], P1); fma2(Y0, W2[WY+2], P2);     \
        fma2(Y1, W2[WY+0], P2); fma2(Y1, W2[WY+1], P3); fma2(Y1, W2[WY+2], P4);     \
        if (FIRSTZ) { mul2(Z0, W2[WZ+0], P0); mul2(Z1, W2[WZ+0], P2); }             \
        else        { fma2(Z0, W2[WZ+0], P0); fma2(Z1, W2[WZ+0], P2); }             \
        fma2(Z0, W2[WZ+1], P1); fma2(Z0, W2[WZ+2], P2);                             \
        fma2(Z1, W2[WZ+1], P3); fma2(Z1, W2[WZ+2], P4);                             \
    }

// One plane: STS current prefetched regs, prefetch next plane, sync, 3 rows of
// accumulation, optional store of completed output plane P-1, advance out ptr.
#define BODY(P, DA, DB, RB, _X0,_X1,_Y0,_Y1,_Z0,_Z1, CP0,CP1, _CN0,_CN1, DOSTORE)   \
    do {                                                                            \
        (DA)[0] = va.x; (DA)[1] = va.y; (DA)[2] = va.z; (DA)[3] = va.w;             \
        if (tid < 32) { (DB)[0]=vb.x; (DB)[1]=vb.y; (DB)[2]=vb.z; (DB)[3]=vb.w; }   \
        if (!GUARD || (P) < 63) {                                                   \
            va = __ldg(pA); pA += stA;                                              \
            if (tid < 32) { vb = __ldg(pB); pB += stB; }                            \
        }                                                                           \
        __syncthreads();                                                            \
        {                                                                           \
            u64 &X0=_X0, &X1=_X1, &Y0=_Y0, &Y1=_Y1, &Z0=_Z0, &Z1=_Z1;              \
            u64 &CN0=_CN0, &CN1=_CN1;                                               \
            ROW(RB,   0, 18,  9, 0, true,  false)                                   \
            ROW(RB,  66, 21, 12, 3, false, true)                                    \
            ROW(RB, 132, 24, 15, 6, false, false)                                   \
            if (DOSTORE) {                                                          \
                u64 u0 = add2(X0, CP0), u1 = add2(X1, CP1);                         \
                float o0,o1,o2,o3; unpack2(u0,o0,o1); unpack2(u1,o2,o3);            \
                float4 ov = make_float4(gelu_exact(o0), gelu_exact(o1),             \
                                        gelu_exact(o2), gelu_exact(o3));            \
                *(float4*)optr = ov;                                                \
            }                                                                       \
        }                                                                           \
        optr += 4096;                                                               \
    } while (0)

template<bool GUARD>
__global__ void __launch_bounds__(256, 2)
step_kernel(const float* __restrict__ in, float* __restrict__ out,
            const float* __restrict__ wts)
{
    const int tx  = threadIdx.x;            // 0..15 (w quads)
    const int ty  = threadIdx.y;            // 0..15 (h rows)
    const int tid = ty * 16 + tx;
    const int h0  = blockIdx.x * 16;
    const int c   = blockIdx.y;
    const int b   = blockIdx.z;

    const float* vin  = in  + (size_t)(b * CC + c) * VOL;
    float*       vout = out + (size_t)(b * CC + c) * VOL;

    u64 W2[27];
#pragma unroll
    for (int i = 0; i < 27; ++i) {
        float w = __ldg(&wts[c * 27 + i]);
        W2[i] = pack2(w, w);
    }

    __shared__ float slab[2][18 * 66];
    if (tid < 72) {                          // zero W-halo cols of both slabs once
        int s = tid / 36, k = tid % 36;
        slab[s][(k % 18) * 66 + ((k / 18) ? 65 : 0)] = 0.f;
    }

    // Loaders: rows 0..17 (18x64 floats = 288 float4; tid does #tid, tid<32 also #256+tid).
    const int r0 = tid >> 4, cq = tid & 15;
    const int gh0 = h0 - 1 + r0;
    const bool v0 = (gh0 >= 0) && (gh0 < 64);
    const float4* pA = v0 ? (const float4*)vin + gh0 * 16 + cq : &g_zero4;
    const int stA = v0 ? 1024 : 0;          // float4 per plane (or pinned to zero)
    float* dA0 = &slab[0][r0 * 66 + 1 + 4 * cq];
    float* dA1 = &slab[1][r0 * 66 + 1 + 4 * cq];

    const int r1 = 16 + (tid >> 4);
    const int gh1 = h0 - 1 + r1;
    const bool v1 = (tid < 32) && (gh1 < 64);
    const float4* pB = v1 ? (const float4*)vin + gh1 * 16 + cq : &g_zero4;
    const int stB = v1 ? 1024 : 0;
    float* dB0 = &slab[0][r1 * 66 + 1 + 4 * cq];
    float* dB1 = &slab[1][r1 * 66 + 1 + 4 * cq];

    const float* rb0 = &slab[0][ty * 66 + 4 * tx];
    const float* rb1 = &slab[1][ty * 66 + 4 * tx];

    float4 va = __ldg(pA); pA += stA;
    float4 vb = make_float4(0.f, 0.f, 0.f, 0.f);
    if (tid < 32) { vb = __ldg(pB); pB += stB; }

    u64 x0=0,x1=0,y0=0,y1=0,z0=0,z1=0;       // rotating accumulators (static roles)
    u64 cA0=0,cA1=0,cB0=0,cB1=0;             // rotating residual centers

    float* optr = vout + ((h0 + ty) * 64 + 4 * tx) - 4096;

    // Peel planes 0..3 to align the period-6 pattern.
    BODY(0, dA0, dB0, rb0, x0,x1,y0,y1,z0,z1, cA0,cA1, cB0,cB1, false);
    BODY(1, dA1, dB1, rb1, y0,y1,z0,z1,x0,x1, cB0,cB1, cA0,cA1, true);
    BODY(2, dA0, dB0, rb0, z0,z1,x0,x1,y0,y1, cA0,cA1, cB0,cB1, true);
    BODY(3, dA1, dB1, rb1, x0,x1,y0,y1,z0,z1, cB0,cB1, cA0,cA1, true);

#pragma unroll 1
    for (int i = 0; i < 10; ++i) {           // planes 4..63
        const int p = 4 + 6 * i;
        BODY(p+0, dA0, dB0, rb0, y0,y1,z0,z1,x0,x1, cA0,cA1, cB0,cB1, true);
        BODY(p+1, dA1, dB1, rb1, z0,z1,x0,x1,y0,y1, cB0,cB1, cA0,cA1, true);
        BODY(p+2, dA0, dB0, rb0, x0,x1,y0,y1,z0,z1, cA0,cA1, cB0,cB1, true);
        BODY(p+3, dA1, dB1, rb1, y0,y1,z0,z1,x0,x1, cB0,cB1, cA0,cA1, true);
        BODY(p+4, dA0, dB0, rb0, z0,z1,x0,x1,y0,y1, cA0,cA1, cB0,cB1, true);
        BODY(p+5, dA1, dB1, rb1, x0,x1,y0,y1,z0,z1, cB0,cB1, cA0,cA1, true);
    }

    // out(63): kz2(plane64)=0; partial lives in y, center63 in cA.
    {
        u64 u0 = add2(y0, cA0), u1 = add2(y1, cA1);
        float o0,o1,o2,o3; unpack2(u0,o0,o1); unpack2(u1,o2,o3);
        float4 ov = make_float4(gelu_exact(o0), gelu_exact(o1),
                                gelu_exact(o2), gelu_exact(o3));
        *(float4*)optr = ov;
    }
}

extern "C" void kernel_launch(void* const* d_in, const int* in_sizes, int n_in,
                              void* d_out, int out_size)
{
    const float* x = (const float*)d_in[0];
    const float* w = (const float*)d_in[1];
    float* out = (float*)d_out;

    float *sA = nullptr, *sB = nullptr;
    cudaGetSymbolAddress((void**)&sA, g_sA);
    cudaGetSymbolAddress((void**)&sB, g_sB);

    dim3 grid(4, CC, 4);
    dim3 blk(16, 16);

    // Step 0 reads the harness buffer (guard the plane-64 prefetch);
    // steps 1..7 read padded scratch (unguarded prefetch into padding).
    step_kernel<true ><<<grid, blk>>>(x,  sA,  w);
    step_kernel<false><<<grid, blk>>>(sA, sB,  w);
    step_kernel<false><<<grid, blk>>>(sB, sA,  w);
    step_kernel<false><<<grid, blk>>>(sA, sB,  w);
    step_kernel<false><<<grid, blk>>>(sB, sA,  w);
    step_kernel<false><<<grid, blk>>>(sA, sB,  w);
    step_kernel<false><<<grid, blk>>>(sB, sA,  w);
    step_kernel<false><<<grid, blk>>>(sA, out, w);
}